// round 10
// baseline (speedup 1.0000x reference)
#include <cuda_runtime.h>

#define HWD (96*96*96)        // 884736
#define NB  4
#define NVOX (NB*HWD)         // 3538944
#define Q4  (HWD/4)           // 221184 float4 groups per (b, channel)
#define BLOCK 256
#define GPT 2                 // float4-groups per thread (8 voxels)
#define BPB (Q4 / (GPT * BLOCK))   // 432 blocks per batch, exact
#define GRID (NB * BPB)            // 1728

__device__ double       g_sum    = 0.0;
__device__ int          g_cnt    = 0;
__device__ unsigned int g_retire = 0u;

__device__ __forceinline__ void cp_async16(void* smem_dst, const void* gsrc) {
    unsigned saddr = (unsigned)__cvta_generic_to_shared(smem_dst);
    asm volatile("cp.async.cg.shared.global [%0], [%1], 16;"
                 :: "r"(saddr), "l"(gsrc) : "memory");
}

// acos via Abramowitz-Stegun 4.4.45 (4 coeff): abs err <= 6.7e-5 rad.
__device__ __forceinline__ float fast_acosf(float x) {
    float ax = fabsf(x);
    float t  = 1.0f - ax;
    float s  = t * rsqrtf(t);                 // sqrt(1-ax), MUFU.RSQ
    float p  = fmaf(ax, -0.0187293f, 0.0742610f);
    p = fmaf(ax, p, -0.2121144f);
    p = fmaf(ax, p,  1.5707288f);
    float a = s * p;
    return (x >= 0.0f) ? a : (3.14159265358979f - a);
}

// q (mean eig), p (spread), cp = cos(acos(r)/3); normalization folded via rs^3.
__device__ __forceinline__ void eig_qpc(
    float a00, float a01, float a02, float a11, float a12, float a22,
    float& q, float& p, float& cp)
{
    q = (a00 + a11 + a22) * (1.0f / 3.0f);
    float c00 = a00 - q, c11 = a11 - q, c22 = a22 - q;
    float p2 = c00*c00 + c11*c11 + c22*c22
             + 2.0f * (a01*a01 + a02*a02 + a12*a12);
    float p2s = p2 * (1.0f / 6.0f);
    float rs  = (p2s > 0.0f) ? rsqrtf(p2s) : 0.0f;   // MUFU.RSQ
    p = p2s * rs;                                     // = sqrt(p2/6)

    float detC = c00 * (c11*c22 - a12*a12)
               - a01 * (a01*c22 - a12*a02)
               + a02 * (a01*a12 - c11*a02);
    float rs3 = rs * rs * rs;
    float r = 0.5f * detC * rs3;
    r = fminf(fmaxf(r, -1.0f + 1e-7f), 1.0f - 1e-7f);
    float phi = fast_acosf(r) * (1.0f / 3.0f);
    cp = __cosf(phi);   // phi in [0, pi/3]
}

__device__ __forceinline__ float f4_get(const float4& v, int lane) {
    switch (lane) {
        case 0: return v.x;
        case 1: return v.y;
        case 2: return v.z;
        default: return v.w;
    }
}

__global__ void __launch_bounds__(BLOCK, 4)
ani_loss_kernel(const float*  __restrict__ input,
                const float*  __restrict__ target,
                const int*    __restrict__ mask,
                const float*  __restrict__ gt_mean,
                const float*  __restrict__ gt_std,
                float*        __restrict__ out)
{
    __shared__ float4 stg[12 * BLOCK];   // target channels, both groups

    int b  = blockIdx.x / BPB;
    int s0 = (blockIdx.x - b * BPB) * (GPT * BLOCK) + threadIdx.x;  // group 0
    // group 1 is s0 + BLOCK

    const float4* in4 = (const float4*)input  + (size_t)b * 6 * Q4 + s0;
    const float4* tg4 = (const float4*)target + (size_t)b * 6 * Q4 + s0;
    const int4*   mk4 = (const int4*)mask     + (size_t)b * Q4 + s0;

    float mean[6], stdv[6];
    #pragma unroll
    for (int c = 0; c < 6; c++) {
        mean[c] = __ldg(&gt_mean[c]);
        stdv[c] = __ldg(&gt_std[c]);
    }

    // ---- masks ----
    int4 mi0 = __ldcs(mk4);
    int4 mi1 = __ldcs(mk4 + BLOCK);

    // ---- prefetch ALL target channels (both groups) into smem ----
    #pragma unroll
    for (int c = 0; c < 6; c++) {
        cp_async16(&stg[(2*c + 0) * BLOCK + threadIdx.x], &tg4[c * Q4]);
        cp_async16(&stg[(2*c + 1) * BLOCK + threadIdx.x], &tg4[c * Q4 + BLOCK]);
    }
    asm volatile("cp.async.commit_group;" ::: "memory");

    float iani[2][4];

    // ---- input group 0 ----
    {
        float4 x[6];
        #pragma unroll
        for (int c = 0; c < 6; c++)
            x[c] = __ldcs(&in4[c * Q4]);
        #pragma unroll
        for (int lane = 0; lane < 4; lane++) {
            float a[6];
            #pragma unroll
            for (int c = 0; c < 6; c++)
                a[c] = fmaf(f4_get(x[c], lane), stdv[c], mean[c]);
            float q, p, cp;
            eig_qpc(a[0], a[1], a[2], a[3], a[4], a[5], q, p, cp);
            iani[0][lane] = 3.0f * p * cp;
        }
    }
    // ---- input group 1 ----
    {
        float4 x[6];
        #pragma unroll
        for (int c = 0; c < 6; c++)
            x[c] = __ldcs(&in4[c * Q4 + BLOCK]);
        #pragma unroll
        for (int lane = 0; lane < 4; lane++) {
            float a[6];
            #pragma unroll
            for (int c = 0; c < 6; c++)
                a[c] = fmaf(f4_get(x[c], lane), stdv[c], mean[c]);
            float q, p, cp;
            eig_qpc(a[0], a[1], a[2], a[3], a[4], a[5], q, p, cp);
            iani[1][lane] = 3.0f * p * cp;
        }
    }

    // ---- targets from smem ----
    asm volatile("cp.async.wait_group 0;" ::: "memory");

    int mlane[2][4] = {{mi0.x, mi0.y, mi0.z, mi0.w},
                       {mi1.x, mi1.y, mi1.z, mi1.w}};
    float lsum = 0.0f;
    int   lcnt = 0;

    #pragma unroll
    for (int g = 0; g < 2; g++) {
        float4 x[6];
        #pragma unroll
        for (int c = 0; c < 6; c++)
            x[c] = stg[(2*c + g) * BLOCK + threadIdx.x];
        #pragma unroll
        for (int lane = 0; lane < 4; lane++) {
            float a[6];
            #pragma unroll
            for (int c = 0; c < 6; c++)
                a[c] = fmaf(f4_get(x[c], lane), stdv[c], mean[c]);
            float q, p, cp;
            eig_qpc(a[0], a[1], a[2], a[3], a[4], a[5], q, p, cp);
            float tani = q - p * cp;
            float mf = (float)mlane[g][lane];
            lsum += fabsf(iani[g][lane] - tani) * mf;
            lcnt += mlane[g][lane];
        }
    }

    // ---- reduction ----
    #pragma unroll
    for (int o = 16; o > 0; o >>= 1) {
        lsum += __shfl_down_sync(0xFFFFFFFFu, lsum, o);
        lcnt += __shfl_down_sync(0xFFFFFFFFu, lcnt, o);
    }

    __shared__ float ssum[8];
    __shared__ int   scnt[8];
    __shared__ bool  isLast;
    int wid = threadIdx.x >> 5;
    int lid = threadIdx.x & 31;
    if (lid == 0) { ssum[wid] = lsum; scnt[wid] = lcnt; }
    __syncthreads();

    if (wid == 0) {
        float bs = (lid < (BLOCK >> 5)) ? ssum[lid] : 0.0f;
        int   bc = (lid < (BLOCK >> 5)) ? scnt[lid] : 0;
        #pragma unroll
        for (int o = 4; o > 0; o >>= 1) {
            bs += __shfl_down_sync(0xFFFFFFFFu, bs, o);
            bc += __shfl_down_sync(0xFFFFFFFFu, bc, o);
        }
        if (lid == 0) {
            atomicAdd(&g_sum, (double)bs);
            atomicAdd(&g_cnt, bc);
            __threadfence();
            unsigned t = atomicAdd(&g_retire, 1u);
            isLast = (t == (unsigned)(gridDim.x - 1));
        }
    }
    __syncthreads();

    // Last block finalizes and resets accumulators (graph-replay safe).
    if (isLast && threadIdx.x == 0) {
        double s_tot = atomicAdd(&g_sum, 0.0);
        int    c_tot = atomicAdd(&g_cnt, 0);
        double n = (c_tot < 1) ? 1.0 : (double)c_tot;
        out[0] = (float)(s_tot / n);
        atomicExch((unsigned long long*)&g_sum, 0ull);
        atomicExch(&g_cnt, 0);
        __threadfence();
        atomicExch(&g_retire, 0u);
    }
}

extern "C" void kernel_launch(void* const* d_in, const int* in_sizes, int n_in,
                              void* d_out, int out_size)
{
    const float* input   = (const float*)d_in[0];
    const float* target  = (const float*)d_in[1];
    const int*   mask    = (const int*)d_in[2];
    const float* gt_mean = (const float*)d_in[3];
    const float* gt_std  = (const float*)d_in[4];
    float* out = (float*)d_out;

    ani_loss_kernel<<<GRID, BLOCK>>>(input, target, mask, gt_mean, gt_std, out);
}